// round 3
// baseline (speedup 1.0000x reference)
#include <cuda_runtime.h>
#include <float.h>

#define NPTS 2048
#define BATCH 8
#define MTOT (BATCH * NPTS)

// ---------------- scratch (device globals; no runtime allocation) ------------
__device__ float g_G[(size_t)BATCH * NPTS * NPTS];   // 128 MB Gram/dist scratch
__device__ float g_xcat[(size_t)MTOT * 512];         // x1|x2|x3|x4 concatenated
__device__ float g_YZ[(size_t)MTOT * 512];           // [Y | Z] per edge layer
__device__ float g_xlocal[(size_t)MTOT * 512];
__device__ float g_xemb[(size_t)MTOT * 1024];
__device__ float g_h1[(size_t)MTOT * 256];
__device__ float g_h2[(size_t)MTOT * 256];
__device__ float g_xx[MTOT];
__device__ int   g_idx[MTOT * 20];
__device__ float g_glob[BATCH * 1024];
__device__ float g_gbias[BATCH * 256];
__device__ float g_Wc[512 * 128];                    // [W1 ; W2-W1]

// ---------------- tiled GEMM: out[m,o] = sum_c X[m,c]*W[o,c] -----------------
// Block tile 128(M) x 64(O), k-tile 16, 256 threads, 8x4 per-thread micro-tile,
// double-buffered shared memory.
// MODE 0: raw   MODE 1: lrelu(s*v+t)   MODE 2: lrelu(s*(v+gadd[b,o])+t)
// MODE 3: v + t[o]
template <int MODE>
__global__ void __launch_bounds__(256) gemm_nt(
    const float* __restrict__ Xb, int ldx, long bsX,
    const float* __restrict__ Wb, int ldw, long bsW,
    float* __restrict__ Ob, int ldo, long bsO,
    int M, int C, int O,
    const float* __restrict__ s, const float* __restrict__ t,
    const float* __restrict__ gadd)
{
    __shared__ float Xs[2][16][132];
    __shared__ float Ws[2][16][68];
    const float* X = Xb + (long)blockIdx.z * bsX;
    const float* W = Wb + (long)blockIdx.z * bsW;
    float* Out = Ob + (long)blockIdx.z * bsO;
    const int m0 = blockIdx.y * 128, o0 = blockIdx.x * 64;
    const int tid = threadIdx.x;

    // loader mapping: lc = c within k-tile, lr = row-group
    const int lc = tid & 15, lr = tid >> 4;        // lr in 0..15
    // compute mapping: tm row-group of 8, to col-group of 4
    const int tm = tid & 15, to = tid >> 4;

    float acc[8][4];
#pragma unroll
    for (int i = 0; i < 8; i++)
#pragma unroll
        for (int j = 0; j < 4; j++) acc[i][j] = 0.f;

    const int nk = (C + 15) >> 4;

    // prologue: load k-tile 0 into buffer 0
    {
        const int c = lc;
        const bool cok = (c < C);
#pragma unroll
        for (int i = 0; i < 8; i++) {
            int m = m0 + lr * 8 + i;
            Xs[0][lc][lr * 8 + i] = (cok && m < M) ? X[(long)m * ldx + c] : 0.f;
        }
#pragma unroll
        for (int j = 0; j < 4; j++) {
            int o = o0 + lr * 4 + j;
            Ws[0][lc][lr * 4 + j] = (cok && o < O) ? W[(long)o * ldw + c] : 0.f;
        }
    }
    __syncthreads();

    for (int kt = 0; kt < nk; kt++) {
        const int buf = kt & 1;
        float px[8], pw[4];
        const bool more = (kt + 1 < nk);
        if (more) {
            const int c = (kt + 1) * 16 + lc;
            const bool cok = (c < C);
#pragma unroll
            for (int i = 0; i < 8; i++) {
                int m = m0 + lr * 8 + i;
                px[i] = (cok && m < M) ? X[(long)m * ldx + c] : 0.f;
            }
#pragma unroll
            for (int j = 0; j < 4; j++) {
                int o = o0 + lr * 4 + j;
                pw[j] = (cok && o < O) ? W[(long)o * ldw + c] : 0.f;
            }
        }

#pragma unroll
        for (int kk = 0; kk < 16; kk++) {
            float xf[8], wf[4];
#pragma unroll
            for (int i = 0; i < 8; i++) xf[i] = Xs[buf][kk][tm * 8 + i];
#pragma unroll
            for (int j = 0; j < 4; j++) wf[j] = Ws[buf][kk][to * 4 + j];
#pragma unroll
            for (int i = 0; i < 8; i++)
#pragma unroll
                for (int j = 0; j < 4; j++) acc[i][j] += xf[i] * wf[j];
        }

        if (more) {
            const int nb = buf ^ 1;
#pragma unroll
            for (int i = 0; i < 8; i++) Xs[nb][lc][lr * 8 + i] = px[i];
#pragma unroll
            for (int j = 0; j < 4; j++) Ws[nb][lc][lr * 4 + j] = pw[j];
        }
        __syncthreads();
    }

#pragma unroll
    for (int i = 0; i < 8; i++) {
        int m = m0 + tm * 8 + i;
        if (m >= M) continue;
#pragma unroll
        for (int j = 0; j < 4; j++) {
            int o = o0 + to * 4 + j;
            if (o >= O) continue;
            float v = acc[i][j];
            if (MODE == 1) { v = s[o] * v + t[o]; v = v >= 0.f ? v : 0.2f * v; }
            else if (MODE == 2) {
                v = s[o] * (v + gadd[(m >> 11) * O + o]) + t[o];
                v = v >= 0.f ? v : 0.2f * v;
            }
            else if (MODE == 3) { v = v + t[o]; }
            Out[(long)m * ldo + o] = v;
        }
    }
}

// ---------------- squared row norms ------------------------------------------
__global__ void rownorm_kernel(const float* __restrict__ X, int ldx, int C,
                               float* __restrict__ xx)
{
    int m = blockIdx.x * blockDim.x + threadIdx.x;
    if (m >= MTOT) return;
    const float* p = X + (long)m * ldx;
    float a = 0.f;
    for (int c = 0; c < C; c++) a += p[c] * p[c];
    xx[m] = a;
}

// ---------------- top-20 smallest of d_j = xx_i + xx_j - 2*G[i,j] ------------
// Iterative argmin with lowest-index tiebreak (matches stable lax.top_k).
__global__ void __launch_bounds__(256) topk_kernel(
    const float* __restrict__ G, const float* __restrict__ xx,
    int* __restrict__ idxout)
{
    __shared__ float d[NPTS];
    __shared__ float wv[8];
    __shared__ int wi[8];
    int row = blockIdx.x;
    int b = row >> 11;
    const float* g = G + (long)row * NPTS;
    const float* xxb = xx + (b << 11);
    float xi = xx[row];
    int tid = threadIdx.x;

    for (int j = tid; j < NPTS; j += 256) d[j] = xi + xxb[j] - 2.f * g[j];
    __syncthreads();

    for (int it = 0; it < 20; it++) {
        float best = FLT_MAX;
        int bi = 1 << 30;
        for (int j = tid; j < NPTS; j += 256) {
            float v = d[j];
            if (v < best) { best = v; bi = j; }   // within-thread: first (lowest j) wins ties
        }
#pragma unroll
        for (int off = 16; off > 0; off >>= 1) {
            float ov = __shfl_down_sync(0xFFFFFFFFu, best, off);
            int oi = __shfl_down_sync(0xFFFFFFFFu, bi, off);
            if (ov < best || (ov == best && oi < bi)) { best = ov; bi = oi; }
        }
        if ((tid & 31) == 0) { wv[tid >> 5] = best; wi[tid >> 5] = bi; }
        __syncthreads();
        if (tid == 0) {
            best = wv[0]; bi = wi[0];
#pragma unroll
            for (int w = 1; w < 8; w++)
                if (wv[w] < best || (wv[w] == best && wi[w] < bi)) { best = wv[w]; bi = wi[w]; }
            idxout[row * 20 + it] = bi;
            d[bi] = FLT_MAX;
        }
        __syncthreads();
    }
}

// ---------------- build combined weight [W1 ; W2-W1] -------------------------
__global__ void prep_wc_kernel(const float* __restrict__ w, float* __restrict__ wc,
                               int O, int C)
{
    int i = blockIdx.x * blockDim.x + threadIdx.x;
    if (i >= O * C) return;
    int o = i / C, c = i - o * C;
    float w1 = w[(long)o * 2 * C + c];
    float w2 = w[(long)o * 2 * C + C + c];
    wc[(long)o * C + c] = w1;
    wc[(long)(O + o) * C + c] = w2 - w1;
}

// ---------------- gather-max over k neighbors + epilogue ---------------------
// out[bn,o] = lrelu(s_o * (max_k Y[b,idx[k],o] + Z[bn,o]) + t_o)
__global__ void __launch_bounds__(128) edge_max_kernel(
    const float* __restrict__ YZ, int ldyz,
    const int* __restrict__ idx,
    const float* __restrict__ s,
    const float* __restrict__ t,
    float* __restrict__ out, int ldo, int O)
{
    __shared__ int nb[20];
    int bn = blockIdx.x;
    int bbase = (bn >> 11) << 11;
    if (threadIdx.x < 20) nb[threadIdx.x] = idx[bn * 20 + threadIdx.x];
    __syncthreads();
    for (int o = threadIdx.x; o < O; o += 128) {
        float z = YZ[(long)bn * ldyz + O + o];
        float m = -FLT_MAX;
#pragma unroll
        for (int kk = 0; kk < 20; kk++) {
            float y = YZ[(long)(bbase + nb[kk]) * ldyz + o];
            m = fmaxf(m, y);
        }
        float v = s[o] * (m + z) + t[o];
        out[(long)bn * ldo + o] = v >= 0.f ? v : 0.2f * v;
    }
}

// ---------------- global max over N ------------------------------------------
__global__ void maxreduce_kernel(const float* __restrict__ xemb,
                                 float* __restrict__ glob)
{
    int o = blockIdx.x * blockDim.x + threadIdx.x;   // 0..1023
    int b = blockIdx.y;
    const float* p = xemb + (long)b * NPTS * 1024 + o;
    float m = -FLT_MAX;
    for (int n = 0; n < NPTS; n++) m = fmaxf(m, p[(long)n * 1024]);
    glob[b * 1024 + o] = m;
}

// ---------------- per-batch global-feature bias for h1 -----------------------
__global__ void gbias_kernel(const float* __restrict__ h1w,
                             const float* __restrict__ glob,
                             float* __restrict__ gb)
{
    __shared__ float gsh[1024];
    int b = blockIdx.x, o = threadIdx.x;
    for (int c = threadIdx.x; c < 1024; c += 256) gsh[c] = glob[b * 1024 + c];
    __syncthreads();
    const float* wr = h1w + (long)o * 1536 + 512;
    float acc = 0.f;
    for (int c = 0; c < 1024; c++) acc += gsh[c] * wr[c];
    gb[b * 256 + o] = acc;
}

// ---------------- host orchestration -----------------------------------------
static inline dim3 ggrid(int M, int O, int Z) {
    return dim3((O + 63) / 64, (M + 127) / 128, Z);
}

static void run_edge_layer(const float* X, int ldx, int C, int O,
                           const float* w, const float* s, const float* t,
                           float* pG, float* pxx, int* pidx, float* pWc,
                           float* pYZ, float* outcol)
{
    // 1. squared norms
    rownorm_kernel<<<(MTOT + 255) / 256, 256>>>(X, ldx, C, pxx);
    // 2. Gram matrix per batch: G[b] = X[b] X[b]^T
    gemm_nt<0><<<ggrid(NPTS, NPTS, BATCH), 256>>>(
        X, ldx, (long)NPTS * ldx, X, ldx, (long)NPTS * ldx,
        pG, NPTS, (long)NPTS * NPTS, NPTS, C, NPTS,
        nullptr, nullptr, nullptr);
    // 3. top-20 neighbors
    topk_kernel<<<MTOT, 256>>>(pG, pxx, pidx);
    // 4. combined weight [W1; W2-W1]
    prep_wc_kernel<<<(O * C + 255) / 256, 256>>>(w, pWc, O, C);
    // 5. YZ = X @ Wc^T  (raw, activation after max)
    gemm_nt<0><<<ggrid(MTOT, 2 * O, 1), 256>>>(
        X, ldx, 0L, pWc, C, 0L, pYZ, 2 * O, 0L,
        MTOT, C, 2 * O, nullptr, nullptr, nullptr);
    // 6. gather-max + lrelu epilogue, write directly into xcat column slice
    edge_max_kernel<<<MTOT, 128>>>(pYZ, 2 * O, pidx, s, t, outcol, 512, O);
}

extern "C" void kernel_launch(void* const* d_in, const int* in_sizes, int n_in,
                              void* d_out, int out_size)
{
    const float* xyz    = (const float*)d_in[0];
    const float* ec1_w  = (const float*)d_in[1];
    const float* ec1_s  = (const float*)d_in[2];
    const float* ec1_t  = (const float*)d_in[3];
    const float* ec2_w  = (const float*)d_in[4];
    const float* ec2_s  = (const float*)d_in[5];
    const float* ec2_t  = (const float*)d_in[6];
    const float* ec3_w  = (const float*)d_in[7];
    const float* ec3_s  = (const float*)d_in[8];
    const float* ec3_t  = (const float*)d_in[9];
    const float* ec4_w  = (const float*)d_in[10];
    const float* ec4_s  = (const float*)d_in[11];
    const float* ec4_t  = (const float*)d_in[12];
    const float* fuse_w = (const float*)d_in[13];
    const float* fuse_s = (const float*)d_in[14];
    const float* fuse_t = (const float*)d_in[15];
    const float* emb_w  = (const float*)d_in[16];
    const float* emb_s  = (const float*)d_in[17];
    const float* emb_t  = (const float*)d_in[18];
    const float* h1_w   = (const float*)d_in[19];
    const float* h1_s   = (const float*)d_in[20];
    const float* h1_t   = (const float*)d_in[21];
    const float* h2_w   = (const float*)d_in[22];
    const float* h2_s   = (const float*)d_in[23];
    const float* h2_t   = (const float*)d_in[24];
    const float* h3_w   = (const float*)d_in[25];
    const float* h3_b   = (const float*)d_in[26];
    float* out = (float*)d_out;

    float *pG, *pxcat, *pYZ, *pxloc, *pxemb, *ph1, *ph2, *pxx, *pWc, *pglob, *pgb;
    int* pidx;
    cudaGetSymbolAddress((void**)&pG, g_G);
    cudaGetSymbolAddress((void**)&pxcat, g_xcat);
    cudaGetSymbolAddress((void**)&pYZ, g_YZ);
    cudaGetSymbolAddress((void**)&pxloc, g_xlocal);
    cudaGetSymbolAddress((void**)&pxemb, g_xemb);
    cudaGetSymbolAddress((void**)&ph1, g_h1);
    cudaGetSymbolAddress((void**)&ph2, g_h2);
    cudaGetSymbolAddress((void**)&pxx, g_xx);
    cudaGetSymbolAddress((void**)&pWc, g_Wc);
    cudaGetSymbolAddress((void**)&pglob, g_glob);
    cudaGetSymbolAddress((void**)&pgb, g_gbias);
    cudaGetSymbolAddress((void**)&pidx, g_idx);

    // EdgeConv stack; each layer writes its output into a column slice of xcat
    run_edge_layer(xyz,         3,   3,   64,  ec1_w, ec1_s, ec1_t, pG, pxx, pidx, pWc, pYZ, pxcat + 0);
    run_edge_layer(pxcat + 0,   512, 64,  64,  ec2_w, ec2_s, ec2_t, pG, pxx, pidx, pWc, pYZ, pxcat + 64);
    run_edge_layer(pxcat + 64,  512, 64,  128, ec3_w, ec3_s, ec3_t, pG, pxx, pidx, pWc, pYZ, pxcat + 128);
    run_edge_layer(pxcat + 128, 512, 128, 256, ec4_w, ec4_s, ec4_t, pG, pxx, pidx, pWc, pYZ, pxcat + 256);

    // fuse: (16384,512) -> 512, lrelu
    gemm_nt<1><<<ggrid(MTOT, 512, 1), 256>>>(
        pxcat, 512, 0L, fuse_w, 512, 0L, pxloc, 512, 0L,
        MTOT, 512, 512, fuse_s, fuse_t, nullptr);
    // emb: 512 -> 1024, lrelu
    gemm_nt<1><<<ggrid(MTOT, 1024, 1), 256>>>(
        pxloc, 512, 0L, emb_w, 512, 0L, pxemb, 1024, 0L,
        MTOT, 512, 1024, emb_s, emb_t, nullptr);
    // global max over N
    maxreduce_kernel<<<dim3(4, BATCH), 256>>>(pxemb, pglob);
    // per-batch bias from global feature through h1_w[:,512:]
    gbias_kernel<<<BATCH, 256>>>(h1_w, pglob, pgb);
    // h1: 512 -> 256 with per-batch gadd, lrelu (ldw = 1536, first 512 cols)
    gemm_nt<2><<<ggrid(MTOT, 256, 1), 256>>>(
        pxloc, 512, 0L, h1_w, 1536, 0L, ph1, 256, 0L,
        MTOT, 512, 256, h1_s, h1_t, pgb);
    // h2: 256 -> 256, lrelu
    gemm_nt<1><<<ggrid(MTOT, 256, 1), 256>>>(
        ph1, 256, 0L, h2_w, 256, 0L, ph2, 256, 0L,
        MTOT, 256, 256, h2_s, h2_t, nullptr);
    // h3: 256 -> 13, +bias, no activation -> d_out
    gemm_nt<3><<<ggrid(MTOT, 13, 1), 256>>>(
        ph2, 256, 0L, h3_w, 256, 0L, out, 13, 0L,
        MTOT, 256, 13, nullptr, h3_b, nullptr);
}

// round 5
// speedup vs baseline: 1.2369x; 1.2369x over previous
#include <cuda_runtime.h>
#include <float.h>

#define NPTS 2048
#define BATCH 8
#define MTOT (BATCH * NPTS)

// ---------------- scratch (device globals; no runtime allocation) ------------
__device__ float g_G[(size_t)BATCH * NPTS * NPTS];   // 128 MB Gram/dist scratch
__device__ float g_xcat[(size_t)MTOT * 512];         // x1|x2|x3|x4 concatenated
__device__ float g_YZ[(size_t)MTOT * 512];           // [Y | Z] per edge layer
__device__ float g_xlocal[(size_t)MTOT * 512];
__device__ float g_xemb[(size_t)MTOT * 1024];
__device__ float g_h1[(size_t)MTOT * 256];
__device__ float g_h2[(size_t)MTOT * 256];
__device__ float g_xx[MTOT];
__device__ int   g_idx[MTOT * 20];
__device__ float g_glob[BATCH * 1024];
__device__ float g_gbias[BATCH * 256];
__device__ float g_Wc[512 * 128];                    // [W1 ; W2-W1]

// ---------------- generic tiled GEMM: out[m,o] = sum_c X[m,c]*W[o,c] ---------
// (R2 configuration: 64x64 tile, 4x4 microtile — proven baseline)
// MODE 0: raw   MODE 1: lrelu(s*v+t)   MODE 2: lrelu(s*(v+gadd[b,o])+t)
// MODE 3: v + t[o]
template <int MODE>
__global__ void __launch_bounds__(256) gemm_nt(
    const float* __restrict__ Xb, int ldx, long bsX,
    const float* __restrict__ Wb, int ldw, long bsW,
    float* __restrict__ Ob, int ldo, long bsO,
    int M, int C, int O,
    const float* __restrict__ s, const float* __restrict__ t,
    const float* __restrict__ gadd)
{
    __shared__ float Xs[16][68];
    __shared__ float Ws[16][68];
    const float* X = Xb + (long)blockIdx.z * bsX;
    const float* W = Wb + (long)blockIdx.z * bsW;
    float* Out = Ob + (long)blockIdx.z * bsO;
    int m0 = blockIdx.y * 64, o0 = blockIdx.x * 64;
    int tid = threadIdx.x;
    int tx = tid & 15, ty = tid >> 4;
    int cc = tid & 15, r0 = tid >> 4;

    float acc[4][4];
#pragma unroll
    for (int i = 0; i < 4; i++)
#pragma unroll
        for (int j = 0; j < 4; j++) acc[i][j] = 0.f;

    for (int k0 = 0; k0 < C; k0 += 16) {
        int c = k0 + cc;
        bool cok = (c < C);
#pragma unroll
        for (int i = 0; i < 4; i++) {
            int m = m0 + r0 + i * 16;
            Xs[cc][r0 + i * 16] = (cok && m < M) ? X[(long)m * ldx + c] : 0.f;
            int o = o0 + r0 + i * 16;
            Ws[cc][r0 + i * 16] = (cok && o < O) ? W[(long)o * ldw + c] : 0.f;
        }
        __syncthreads();
#pragma unroll
        for (int kk = 0; kk < 16; kk++) {
            float xf[4], wf[4];
#pragma unroll
            for (int i = 0; i < 4; i++) xf[i] = Xs[kk][ty * 4 + i];
#pragma unroll
            for (int j = 0; j < 4; j++) wf[j] = Ws[kk][tx * 4 + j];
#pragma unroll
            for (int i = 0; i < 4; i++)
#pragma unroll
                for (int j = 0; j < 4; j++) acc[i][j] += xf[i] * wf[j];
        }
        __syncthreads();
    }

#pragma unroll
    for (int i = 0; i < 4; i++) {
        int m = m0 + ty * 4 + i;
        if (m >= M) continue;
#pragma unroll
        for (int j = 0; j < 4; j++) {
            int o = o0 + tx * 4 + j;
            if (o >= O) continue;
            float v = acc[i][j];
            if (MODE == 1) { v = s[o] * v + t[o]; v = v >= 0.f ? v : 0.2f * v; }
            else if (MODE == 2) {
                v = s[o] * (v + gadd[(m >> 11) * O + o]) + t[o];
                v = v >= 0.f ? v : 0.2f * v;
            }
            else if (MODE == 3) { v = v + t[o]; }
            Out[(long)m * ldo + o] = v;
        }
    }
}

// ---------------- squared row norms ------------------------------------------
__global__ void rownorm_kernel(const float* __restrict__ X, int ldx, int C,
                               float* __restrict__ xx)
{
    int m = blockIdx.x * blockDim.x + threadIdx.x;
    if (m >= MTOT) return;
    const float* p = X + (long)m * ldx;
    float a = 0.f;
    for (int c = 0; c < C; c++) a += p[c] * p[c];
    xx[m] = a;
}

// ---------------- top-20 smallest of d_j = xx_i + xx_j - 2*G[i,j] ------------
// Register-cached iterative argmin: 128 threads x 16 values in registers.
// Each thread keeps a cached local (min, idx); per extraction only the winner
// rescans its 16 registers. Lowest-index tiebreak matches stable lax.top_k.
__global__ void __launch_bounds__(128) topk_kernel(
    const float* __restrict__ G, const float* __restrict__ xx,
    int* __restrict__ idxout)
{
    __shared__ float wv[4];
    __shared__ int   wi[4];
    __shared__ int   gsh;

    const int row = blockIdx.x;
    const int b = row >> 11;
    const float* g = G + (long)row * NPTS;
    const float* xxb = xx + (b << 11);
    const float xi = xx[row];
    const int tid = threadIdx.x;
    const int lane = tid & 31, wrp = tid >> 5;

    // load 16 distances per thread: slot i holds j = i*128 + tid (coalesced)
    float v[16];
#pragma unroll
    for (int i = 0; i < 16; i++) {
        int j = i * 128 + tid;
        v[i] = xi + xxb[j] - 2.f * g[j];
    }

    // cached local min (strictly-first wins -> lowest slot -> lowest idx)
    float mv = v[0];
    int ms = 0;
#pragma unroll
    for (int i = 1; i < 16; i++)
        if (v[i] < mv) { mv = v[i]; ms = i; }

    for (int it = 0; it < 20; it++) {
        float bv = mv;
        int bidx = ms * 128 + tid;
        // warp lexicographic reduce
#pragma unroll
        for (int off = 16; off > 0; off >>= 1) {
            float ov = __shfl_down_sync(0xFFFFFFFFu, bv, off);
            int oi = __shfl_down_sync(0xFFFFFFFFu, bidx, off);
            if (ov < bv || (ov == bv && oi < bidx)) { bv = ov; bidx = oi; }
        }
        if (lane == 0) { wv[wrp] = bv; wi[wrp] = bidx; }
        __syncthreads();
        if (tid == 0) {
            bv = wv[0]; bidx = wi[0];
#pragma unroll
            for (int w = 1; w < 4; w++)
                if (wv[w] < bv || (wv[w] == bv && wi[w] < bidx)) { bv = wv[w]; bidx = wi[w]; }
            idxout[row * 20 + it] = bidx;
            gsh = bidx;
        }
        __syncthreads();
        const int gb = gsh;
        if ((gb & 127) == tid) {
            // winner invalidates and rebuilds its cached min
            v[gb >> 7] = FLT_MAX;
            mv = v[0]; ms = 0;
#pragma unroll
            for (int i = 1; i < 16; i++)
                if (v[i] < mv) { mv = v[i]; ms = i; }
        }
        __syncthreads();
    }
}

// ---------------- build combined weight [W1 ; W2-W1] -------------------------
__global__ void prep_wc_kernel(const float* __restrict__ w, float* __restrict__ wc,
                               int O, int C)
{
    int i = blockIdx.x * blockDim.x + threadIdx.x;
    if (i >= O * C) return;
    int o = i / C, c = i - o * C;
    float w1 = w[(long)o * 2 * C + c];
    float w2 = w[(long)o * 2 * C + C + c];
    wc[(long)o * C + c] = w1;
    wc[(long)(O + o) * C + c] = w2 - w1;
}

// ---------------- gather-max over k neighbors + epilogue ---------------------
// out[bn,o] = lrelu(s_o * (max_k Y[b,idx[k],o] + Z[bn,o]) + t_o)
__global__ void __launch_bounds__(128) edge_max_kernel(
    const float* __restrict__ YZ, int ldyz,
    const int* __restrict__ idx,
    const float* __restrict__ s,
    const float* __restrict__ t,
    float* __restrict__ out, int ldo, int O)
{
    __shared__ int nb[20];
    int bn = blockIdx.x;
    int bbase = (bn >> 11) << 11;
    if (threadIdx.x < 20) nb[threadIdx.x] = idx[bn * 20 + threadIdx.x];
    __syncthreads();
    for (int o = threadIdx.x; o < O; o += 128) {
        float z = YZ[(long)bn * ldyz + O + o];
        float m = -FLT_MAX;
#pragma unroll
        for (int kk = 0; kk < 20; kk++) {
            float y = YZ[(long)(bbase + nb[kk]) * ldyz + o];
            m = fmaxf(m, y);
        }
        float v = s[o] * (m + z) + t[o];
        out[(long)bn * ldo + o] = v >= 0.f ? v : 0.2f * v;
    }
}

// ---------------- global max over N (coalesced, 256 blocks) ------------------
__global__ void __launch_bounds__(256) maxreduce_kernel(
    const float* __restrict__ xemb, float* __restrict__ glob)
{
    __shared__ float sh[8][33];
    const int lane = threadIdx.x & 31, grp = threadIdx.x >> 5;
    const int o = blockIdx.x * 32 + lane;
    const int b = blockIdx.y;
    const float* p = xemb + (long)b * NPTS * 1024 + o;
    float m = -FLT_MAX;
    for (int n = grp; n < NPTS; n += 8) m = fmaxf(m, p[(long)n * 1024]);
    sh[grp][lane] = m;
    __syncthreads();
    if (grp == 0) {
#pragma unroll
        for (int r = 1; r < 8; r++) m = fmaxf(m, sh[r][lane]);
        glob[b * 1024 + o] = m;
    }
}

// ---------------- per-batch global-feature bias for h1 -----------------------
__global__ void gbias_kernel(const float* __restrict__ h1w,
                             const float* __restrict__ glob,
                             float* __restrict__ gb)
{
    __shared__ float gsh[1024];
    int b = blockIdx.x, o = threadIdx.x;
    for (int c = threadIdx.x; c < 1024; c += 256) gsh[c] = glob[b * 1024 + c];
    __syncthreads();
    const float* wr = h1w + (long)o * 1536 + 512;
    float acc = 0.f;
    for (int c = 0; c < 1024; c++) acc += gsh[c] * wr[c];
    gb[b * 256 + o] = acc;
}

// ---------------- host orchestration -----------------------------------------
static inline dim3 ggrid(int M, int O, int Z) {
    return dim3((O + 63) / 64, (M + 63) / 64, Z);
}

static void run_edge_layer(const float* X, int ldx, int C, int O,
                           const float* w, const float* s, const float* t,
                           float* pG, float* pxx, int* pidx, float* pWc,
                           float* pYZ, float* outcol)
{
    // order chosen so the ncu capture slot lands on topk for layer 1
    rownorm_kernel<<<(MTOT + 255) / 256, 256>>>(X, ldx, C, pxx);
    gemm_nt<0><<<ggrid(NPTS, NPTS, BATCH), 256>>>(
        X, ldx, (long)NPTS * ldx, X, ldx, (long)NPTS * ldx,
        pG, NPTS, (long)NPTS * NPTS, NPTS, C, NPTS,
        nullptr, nullptr, nullptr);
    prep_wc_kernel<<<(O * C + 255) / 256, 256>>>(w, pWc, O, C);
    topk_kernel<<<MTOT, 128>>>(pG, pxx, pidx);
    gemm_nt<0><<<ggrid(MTOT, 2 * O, 1), 256>>>(
        X, ldx, 0L, pWc, C, 0L, pYZ, 2 * O, 0L,
        MTOT, C, 2 * O, nullptr, nullptr, nullptr);
    edge_max_kernel<<<MTOT, 128>>>(pYZ, 2 * O, pidx, s, t, outcol, 512, O);
}

extern "C" void kernel_launch(void* const* d_in, const int* in_sizes, int n_in,
                              void* d_out, int out_size)
{
    const float* xyz    = (const float*)d_in[0];
    const float* ec1_w  = (const float*)d_in[1];
    const float* ec1_s  = (const float*)d_in[2];
    const float* ec1_t  = (const float*)d_in[3];
    const float* ec2_w  = (const float*)d_in[4];
    const float* ec2_s  = (const float*)d_in[5];
    const float* ec2_t  = (const float*)d_in[6];
    const float* ec3_w  = (const float*)d_in[7];
    const float* ec3_s  = (const float*)d_in[8];
    const float* ec3_t  = (const float*)d_in[9];
    const float* ec4_w  = (const float*)d_in[10];
    const float* ec4_s  = (const float*)d_in[11];
    const float* ec4_t  = (const float*)d_in[12];
    const float* fuse_w = (const float*)d_in[13];
    const float* fuse_s = (const float*)d_in[14];
    const float* fuse_t = (const float*)d_in[15];
    const float* emb_w  = (const float*)d_in[16];
    const float* emb_s  = (const float*)d_in[17];
    const float* emb_t  = (const float*)d_in[18];
    const float* h1_w   = (const float*)d_in[19];
    const float* h1_s   = (const float*)d_in[20];
    const float* h1_t   = (const float*)d_in[21];
    const float* h2_w   = (const float*)d_in[22];
    const float* h2_s   = (const float*)d_in[23];
    const float* h2_t   = (const float*)d_in[24];
    const float* h3_w   = (const float*)d_in[25];
    const float* h3_b   = (const float*)d_in[26];
    float* out = (float*)d_out;

    float *pG, *pxcat, *pYZ, *pxloc, *pxemb, *ph1, *ph2, *pxx, *pWc, *pglob, *pgb;
    int* pidx;
    cudaGetSymbolAddress((void**)&pG, g_G);
    cudaGetSymbolAddress((void**)&pxcat, g_xcat);
    cudaGetSymbolAddress((void**)&pYZ, g_YZ);
    cudaGetSymbolAddress((void**)&pxloc, g_xlocal);
    cudaGetSymbolAddress((void**)&pxemb, g_xemb);
    cudaGetSymbolAddress((void**)&ph1, g_h1);
    cudaGetSymbolAddress((void**)&ph2, g_h2);
    cudaGetSymbolAddress((void**)&pxx, g_xx);
    cudaGetSymbolAddress((void**)&pWc, g_Wc);
    cudaGetSymbolAddress((void**)&pglob, g_glob);
    cudaGetSymbolAddress((void**)&pgb, g_gbias);
    cudaGetSymbolAddress((void**)&pidx, g_idx);

    // EdgeConv stack; each layer writes its output into a column slice of xcat
    run_edge_layer(xyz,         3,   3,   64,  ec1_w, ec1_s, ec1_t, pG, pxx, pidx, pWc, pYZ, pxcat + 0);
    run_edge_layer(pxcat + 0,   512, 64,  64,  ec2_w, ec2_s, ec2_t, pG, pxx, pidx, pWc, pYZ, pxcat + 64);
    run_edge_layer(pxcat + 64,  512, 64,  128, ec3_w, ec3_s, ec3_t, pG, pxx, pidx, pWc, pYZ, pxcat + 128);
    run_edge_layer(pxcat + 128, 512, 128, 256, ec4_w, ec4_s, ec4_t, pG, pxx, pidx, pWc, pYZ, pxcat + 256);

    // fuse: (16384,512) -> 512, lrelu
    gemm_nt<1><<<ggrid(MTOT, 512, 1), 256>>>(
        pxcat, 512, 0L, fuse_w, 512, 0L, pxloc, 512, 0L,
        MTOT, 512, 512, fuse_s, fuse_t, nullptr);
    // emb: 512 -> 1024, lrelu
    gemm_nt<1><<<ggrid(MTOT, 1024, 1), 256>>>(
        pxloc, 512, 0L, emb_w, 512, 0L, pxemb, 1024, 0L,
        MTOT, 512, 1024, emb_s, emb_t, nullptr);
    // global max over N
    maxreduce_kernel<<<dim3(32, BATCH), 256>>>(pxemb, pglob);
    // per-batch bias from global feature through h1_w[:,512:]
    gbias_kernel<<<BATCH, 256>>>(h1_w, pglob, pgb);
    // h1: 512 -> 256 with per-batch gadd, lrelu (ldw = 1536, first 512 cols)
    gemm_nt<2><<<ggrid(MTOT, 256, 1), 256>>>(
        pxloc, 512, 0L, h1_w, 1536, 0L, ph1, 256, 0L,
        MTOT, 512, 256, h1_s, h1_t, pgb);
    // h2: 256 -> 256, lrelu
    gemm_nt<1><<<ggrid(MTOT, 256, 1), 256>>>(
        ph1, 256, 0L, h2_w, 256, 0L, ph2, 256, 0L,
        MTOT, 256, 256, h2_s, h2_t, nullptr);
    // h3: 256 -> 13, +bias, no activation -> d_out
    gemm_nt<3><<<ggrid(MTOT, 13, 1), 256>>>(
        ph2, 256, 0L, h3_w, 256, 0L, out, 13, 0L,
        MTOT, 256, 13, nullptr, h3_b, nullptr);
}

// round 7
// speedup vs baseline: 1.7936x; 1.4501x over previous
#include <cuda_runtime.h>
#include <cuda_bf16.h>
#include <float.h>
#include <stdint.h>

#define NPTS 2048
#define BATCH 8
#define MTOT (BATCH * NPTS)

// ---------------- scratch (device globals; no runtime allocation) ------------
__device__ float g_G[(size_t)BATCH * NPTS * NPTS];   // 128 MB dist/Gram scratch
__device__ float g_xcat[(size_t)MTOT * 512];
__device__ float g_YZ[(size_t)MTOT * 512];
__device__ float g_xlocal[(size_t)MTOT * 512];
__device__ float g_xemb[(size_t)MTOT * 1024];
__device__ float g_h1[(size_t)MTOT * 256];
__device__ float g_h2[(size_t)MTOT * 256];
__device__ float g_xx[MTOT];
__device__ int   g_idx[MTOT * 20];
__device__ float g_glob[BATCH * 1024];
__device__ float g_gbias[BATCH * 256];
__device__ __nv_bfloat16 g_Xb[(size_t)MTOT * 1024];  // split [hi|lo] activations
__device__ __nv_bfloat16 g_Wb[(size_t)1024 * 1024];  // split [hi|lo] weights

// ---------------- warp-mma helpers -------------------------------------------
__device__ __forceinline__ uint32_t smem_u32(const void* p) {
    uint32_t a;
    asm("{ .reg .u64 t; cvta.to.shared.u64 t, %1; cvt.u32.u64 %0, t; }"
        : "=r"(a) : "l"(p));
    return a;
}
__device__ __forceinline__ void ldsm_x4(uint32_t* r, uint32_t addr) {
    asm volatile("ldmatrix.sync.aligned.m8n8.x4.shared.b16 {%0,%1,%2,%3}, [%4];"
                 : "=r"(r[0]), "=r"(r[1]), "=r"(r[2]), "=r"(r[3]) : "r"(addr));
}
__device__ __forceinline__ void mma16816(float* c, const uint32_t* a,
                                         uint32_t b0, uint32_t b1) {
    asm volatile(
        "mma.sync.aligned.m16n8k16.row.col.f32.bf16.bf16.f32 "
        "{%0,%1,%2,%3}, {%4,%5,%6,%7}, {%8,%9}, {%0,%1,%2,%3};"
        : "+f"(c[0]), "+f"(c[1]), "+f"(c[2]), "+f"(c[3])
        : "r"(a[0]), "r"(a[1]), "r"(a[2]), "r"(a[3]), "r"(b0), "r"(b1));
}

#define PITCH 40   // smem row pitch in bf16 (80B: conflict-free ldmatrix)

// ---------------- split-bf16 tensor GEMM: out[m,o] = sum_c X[m,c]*W[o,c] -----
// A, B are split buffers [hi(C) | lo(C)] per row; accumulate
// hi*hi + hi*lo + lo*hi in fp32 via mma.sync.
// MODE 0: raw   MODE 1: lrelu(s*v+t)   MODE 2: lrelu(s*(v+gadd[b,o])+t)
// MODE 3: v + t[o]
template <int MODE>
__global__ void __launch_bounds__(128) gemm_mma(
    const __nv_bfloat16* __restrict__ Ab, int lda, long bsA,
    const __nv_bfloat16* __restrict__ Bb, int ldb, long bsB,
    float* __restrict__ Ob, int ldo, long bsO,
    int M, int C, int O,
    const float* __restrict__ s, const float* __restrict__ t,
    const float* __restrict__ gadd)
{
    __shared__ __align__(16) __nv_bfloat16 sAhi[128 * PITCH];
    __shared__ __align__(16) __nv_bfloat16 sAlo[128 * PITCH];
    __shared__ __align__(16) __nv_bfloat16 sBhi[64 * PITCH];
    __shared__ __align__(16) __nv_bfloat16 sBlo[64 * PITCH];

    const __nv_bfloat16* A = Ab + (long)blockIdx.z * bsA;
    const __nv_bfloat16* B = Bb + (long)blockIdx.z * bsB;
    float* Out = Ob + (long)blockIdx.z * bsO;
    const int m0 = blockIdx.y * 128, o0 = blockIdx.x * 64;
    const int tid = threadIdx.x, lane = tid & 31, w = tid >> 5;
    const __nv_bfloat16 zb = __float2bfloat16(0.0f);

    const uint32_t uAhi = smem_u32(sAhi), uAlo = smem_u32(sAlo);
    const uint32_t uBhi = smem_u32(sBhi), uBlo = smem_u32(sBlo);

    float acc[2][8][4];
#pragma unroll
    for (int i = 0; i < 2; i++)
#pragma unroll
        for (int j = 0; j < 8; j++)
#pragma unroll
            for (int q = 0; q < 4; q++) acc[i][j][q] = 0.f;

    const int nch = (C + 31) >> 5;
    const bool fastv = ((lda & 7) == 0) && ((ldb & 7) == 0) && ((C & 7) == 0);

    for (int cc = 0; cc < nch; cc++) {
        const int kb = cc * 32;
        int vc = C - kb; if (vc > 32) vc = 32;
        const bool fast = fastv && (vc == 32);

        __syncthreads();
        // stage A (128 rows): one row per thread
        {
            const int r = tid;
            const long ra = (long)(m0 + r) * lda;
            if (fast) {
                const uint4* s0 = (const uint4*)(A + ra + kb);
                const uint4* s1 = (const uint4*)(A + ra + C + kb);
                uint4* d0 = (uint4*)(sAhi + r * PITCH);
                uint4* d1 = (uint4*)(sAlo + r * PITCH);
#pragma unroll
                for (int q = 0; q < 4; q++) { d0[q] = s0[q]; d1[q] = s1[q]; }
            } else {
                for (int j = 0; j < 32; j++) {
                    bool ok = (j < vc);
                    sAhi[r * PITCH + j] = ok ? A[ra + kb + j] : zb;
                    sAlo[r * PITCH + j] = ok ? A[ra + C + kb + j] : zb;
                }
            }
        }
        // stage B (64 rows): threads 0..63
        if (tid < 64) {
            const int r = tid;
            const int o = o0 + r;
            if (o < O) {
                const long rb = (long)o * ldb;
                if (fast) {
                    const uint4* s0 = (const uint4*)(B + rb + kb);
                    const uint4* s1 = (const uint4*)(B + rb + C + kb);
                    uint4* d0 = (uint4*)(sBhi + r * PITCH);
                    uint4* d1 = (uint4*)(sBlo + r * PITCH);
#pragma unroll
                    for (int q = 0; q < 4; q++) { d0[q] = s0[q]; d1[q] = s1[q]; }
                } else {
                    for (int j = 0; j < 32; j++) {
                        bool ok = (j < vc);
                        sBhi[r * PITCH + j] = ok ? B[rb + kb + j] : zb;
                        sBlo[r * PITCH + j] = ok ? B[rb + C + kb + j] : zb;
                    }
                }
            } else {
                uint4 z4 = {0, 0, 0, 0};
                uint4* d0 = (uint4*)(sBhi + r * PITCH);
                uint4* d1 = (uint4*)(sBlo + r * PITCH);
#pragma unroll
                for (int q = 0; q < 4; q++) { d0[q] = z4; d1[q] = z4; }
            }
        }
        __syncthreads();

#pragma unroll
        for (int ks = 0; ks < 2; ks++) {
            const int k0 = ks * 16;
            uint32_t ah[2][4], al[2][4], bh[4][4], bl[4][4];
            const int arow = lane & 15;
            const int acol = k0 + ((lane >> 4) << 3);
#pragma unroll
            for (int i = 0; i < 2; i++) {
                uint32_t off = ((w * 32 + i * 16 + arow) * PITCH + acol) * 2;
                ldsm_x4(ah[i], uAhi + off);
                ldsm_x4(al[i], uAlo + off);
            }
            const int seg = lane >> 3;
            const int brow = (lane & 7) + ((seg & 2) << 2);
            const int bcol = k0 + ((seg & 1) << 3);
#pragma unroll
            for (int jp = 0; jp < 4; jp++) {
                uint32_t off = ((jp * 16 + brow) * PITCH + bcol) * 2;
                ldsm_x4(bh[jp], uBhi + off);
                ldsm_x4(bl[jp], uBlo + off);
            }
#pragma unroll
            for (int i = 0; i < 2; i++)
#pragma unroll
                for (int jp = 0; jp < 4; jp++) {
                    mma16816(acc[i][2 * jp],     ah[i], bh[jp][0], bh[jp][1]);
                    mma16816(acc[i][2 * jp + 1], ah[i], bh[jp][2], bh[jp][3]);
                    mma16816(acc[i][2 * jp],     ah[i], bl[jp][0], bl[jp][1]);
                    mma16816(acc[i][2 * jp + 1], ah[i], bl[jp][2], bl[jp][3]);
                    mma16816(acc[i][2 * jp],     al[i], bh[jp][0], bh[jp][1]);
                    mma16816(acc[i][2 * jp + 1], al[i], bh[jp][2], bh[jp][3]);
                }
        }
    }

    // epilogue: fragment layout -> global, fused activation
    const int qrow = lane >> 2, qcol = (lane & 3) * 2;
#pragma unroll
    for (int i = 0; i < 2; i++) {
        const int mA = m0 + w * 32 + i * 16 + qrow;
#pragma unroll
        for (int j = 0; j < 8; j++) {
            const int o = o0 + j * 8 + qcol;
#pragma unroll
            for (int q = 0; q < 4; q++) {
                const int m = mA + ((q >> 1) ? 8 : 0);
                const int oo = o + (q & 1);
                if (oo >= O) continue;
                float v = acc[i][j][q];
                if (MODE == 1) { v = s[oo] * v + t[oo]; v = v >= 0.f ? v : 0.2f * v; }
                else if (MODE == 2) {
                    v = s[oo] * (v + gadd[(m >> 11) * O + oo]) + t[oo];
                    v = v >= 0.f ? v : 0.2f * v;
                }
                else if (MODE == 3) { v = v + t[oo]; }
                Out[(long)m * ldo + oo] = v;
            }
        }
    }
}

// ---------------- fp32 -> split bf16 [hi|lo] ---------------------------------
__global__ void conv_split(const float* __restrict__ X, int ldx, int C, int Mrows,
                           __nv_bfloat16* __restrict__ Y)
{
    long i = (long)blockIdx.x * blockDim.x + threadIdx.x;
    long tot = (long)Mrows * C;
    if (i >= tot) return;
    int m = (int)(i / C), c = (int)(i - (long)m * C);
    float x = X[(long)m * ldx + c];
    __nv_bfloat16 h = __float2bfloat16(x);
    float lo = x - __bfloat162float(h);
    Y[(long)m * 2 * C + c] = h;
    Y[(long)m * 2 * C + C + c] = __float2bfloat16(lo);
}

// ---------------- [W1 ; W2-W1] directly to split bf16 ------------------------
__global__ void prep_wc_split(const float* __restrict__ w,
                              __nv_bfloat16* __restrict__ wcb, int O, int C)
{
    int i = blockIdx.x * blockDim.x + threadIdx.x;
    if (i >= O * C) return;
    int o = i / C, c = i - o * C;
    float w1 = w[(long)o * 2 * C + c];
    float w2 = w[(long)o * 2 * C + C + c];
    __nv_bfloat16 h1b = __float2bfloat16(w1);
    wcb[(long)o * 2 * C + c] = h1b;
    wcb[(long)o * 2 * C + C + c] = __float2bfloat16(w1 - __bfloat162float(h1b));
    float d = w2 - w1;
    __nv_bfloat16 h2b = __float2bfloat16(d);
    wcb[(long)(O + o) * 2 * C + c] = h2b;
    wcb[(long)(O + o) * 2 * C + C + c] = __float2bfloat16(d - __bfloat162float(h2b));
}

// ---------------- squared row norms ------------------------------------------
__global__ void rownorm_kernel(const float* __restrict__ X, int ldx, int C,
                               float* __restrict__ xx)
{
    int m = blockIdx.x * blockDim.x + threadIdx.x;
    if (m >= MTOT) return;
    const float* p = X + (long)m * ldx;
    float a = 0.f;
    for (int c = 0; c < C; c++) a += p[c] * p[c];
    xx[m] = a;
}

// ---------------- top-20 smallest of d_j = xx_i + xx_j - 2*G[i,j] ------------
__global__ void __launch_bounds__(128) topk_kernel(
    const float* __restrict__ G, const float* __restrict__ xx,
    int* __restrict__ idxout)
{
    __shared__ float wv[4];
    __shared__ int   wi[4];
    __shared__ int   gsh;

    const int row = blockIdx.x;
    const int b = row >> 11;
    const float* g = G + (long)row * NPTS;
    const float* xxb = xx + (b << 11);
    const float xi = xx[row];
    const int tid = threadIdx.x;
    const int lane = tid & 31, wrp = tid >> 5;

    float v[16];
#pragma unroll
    for (int i = 0; i < 16; i++) {
        int j = i * 128 + tid;
        v[i] = xi + xxb[j] - 2.f * g[j];
    }
    float mv = v[0];
    int ms = 0;
#pragma unroll
    for (int i = 1; i < 16; i++)
        if (v[i] < mv) { mv = v[i]; ms = i; }

    for (int itk = 0; itk < 20; itk++) {
        float bv = mv;
        int bidx = ms * 128 + tid;
#pragma unroll
        for (int off = 16; off > 0; off >>= 1) {
            float ov = __shfl_down_sync(0xFFFFFFFFu, bv, off);
            int oi = __shfl_down_sync(0xFFFFFFFFu, bidx, off);
            if (ov < bv || (ov == bv && oi < bidx)) { bv = ov; bidx = oi; }
        }
        if (lane == 0) { wv[wrp] = bv; wi[wrp] = bidx; }
        __syncthreads();
        if (tid == 0) {
            bv = wv[0]; bidx = wi[0];
#pragma unroll
            for (int ww = 1; ww < 4; ww++)
                if (wv[ww] < bv || (wv[ww] == bv && wi[ww] < bidx)) { bv = wv[ww]; bidx = wi[ww]; }
            idxout[row * 20 + itk] = bidx;
            gsh = bidx;
        }
        __syncthreads();
        const int gb = gsh;
        if ((gb & 127) == tid) {
            v[gb >> 7] = FLT_MAX;
            mv = v[0]; ms = 0;
#pragma unroll
            for (int i = 1; i < 16; i++)
                if (v[i] < mv) { mv = v[i]; ms = i; }
        }
        __syncthreads();
    }
}

// ---------------- gather-max over k neighbors + epilogue ---------------------
__global__ void __launch_bounds__(128) edge_max_kernel(
    const float* __restrict__ YZ, int ldyz,
    const int* __restrict__ idx,
    const float* __restrict__ s,
    const float* __restrict__ t,
    float* __restrict__ out, int ldo, int O)
{
    __shared__ int nb[20];
    int bn = blockIdx.x;
    int bbase = (bn >> 11) << 11;
    if (threadIdx.x < 20) nb[threadIdx.x] = idx[bn * 20 + threadIdx.x];
    __syncthreads();
    for (int o = threadIdx.x; o < O; o += 128) {
        float z = YZ[(long)bn * ldyz + O + o];
        float m = -FLT_MAX;
#pragma unroll
        for (int kk = 0; kk < 20; kk++) {
            float y = YZ[(long)(bbase + nb[kk]) * ldyz + o];
            m = fmaxf(m, y);
        }
        float v = s[o] * (m + z) + t[o];
        out[(long)bn * ldo + o] = v >= 0.f ? v : 0.2f * v;
    }
}

// ---------------- global max over N (coalesced) ------------------------------
__global__ void __launch_bounds__(256) maxreduce_kernel(
    const float* __restrict__ xemb, float* __restrict__ glob)
{
    __shared__ float sh[8][33];
    const int lane = threadIdx.x & 31, grp = threadIdx.x >> 5;
    const int o = blockIdx.x * 32 + lane;
    const int b = blockIdx.y;
    const float* p = xemb + (long)b * NPTS * 1024 + o;
    float m = -FLT_MAX;
    for (int n = grp; n < NPTS; n += 8) m = fmaxf(m, p[(long)n * 1024]);
    sh[grp][lane] = m;
    __syncthreads();
    if (grp == 0) {
#pragma unroll
        for (int r = 1; r < 8; r++) m = fmaxf(m, sh[r][lane]);
        glob[b * 1024 + o] = m;
    }
}

// ---------------- per-batch global-feature bias for h1 -----------------------
__global__ void gbias_kernel(const float* __restrict__ h1w,
                             const float* __restrict__ glob,
                             float* __restrict__ gb)
{
    __shared__ float gsh[1024];
    int b = blockIdx.x, o = threadIdx.x;
    for (int c = threadIdx.x; c < 1024; c += 256) gsh[c] = glob[b * 1024 + c];
    __syncthreads();
    const float* wr = h1w + (long)o * 1536 + 512;
    float acc = 0.f;
    for (int c = 0; c < 1024; c++) acc += gsh[c] * wr[c];
    gb[b * 256 + o] = acc;
}

// ---------------- host orchestration -----------------------------------------
static inline dim3 tgrid(int M, int O, int Z) {
    return dim3((O + 63) / 64, (M + 127) / 128, Z);
}
static inline int cgrid(long n) { return (int)((n + 255) / 256); }

static void run_edge_layer(const float* X, int ldx, int C, int O,
                           const float* w, const float* s, const float* t,
                           float* pG, float* pxx, int* pidx,
                           __nv_bfloat16* pXb, __nv_bfloat16* pWb,
                           float* pYZ, float* outcol)
{
    conv_split<<<cgrid((long)MTOT * C), 256>>>(X, ldx, C, MTOT, pXb);
    prep_wc_split<<<cgrid(O * C), 256>>>(w, pWb, O, C);
    rownorm_kernel<<<cgrid(MTOT), 256>>>(X, ldx, C, pxx);
    // Gram per batch: G[b] = X[b] X[b]^T  (split bf16, 3-term)
    gemm_mma<0><<<tgrid(NPTS, NPTS, BATCH), 128>>>(
        pXb, 2 * C, (long)NPTS * 2 * C, pXb, 2 * C, (long)NPTS * 2 * C,
        pG, NPTS, (long)NPTS * NPTS, NPTS, C, NPTS, nullptr, nullptr, nullptr);
    topk_kernel<<<MTOT, 128>>>(pG, pxx, pidx);
    // YZ = X @ [W1; W2-W1]^T
    gemm_mma<0><<<tgrid(MTOT, 2 * O, 1), 128>>>(
        pXb, 2 * C, 0L, pWb, 2 * C, 0L, pYZ, 2 * O, 0L,
        MTOT, C, 2 * O, nullptr, nullptr, nullptr);
    edge_max_kernel<<<MTOT, 128>>>(pYZ, 2 * O, pidx, s, t, outcol, 512, O);
}

extern "C" void kernel_launch(void* const* d_in, const int* in_sizes, int n_in,
                              void* d_out, int out_size)
{
    const float* xyz    = (const float*)d_in[0];
    const float* ec1_w  = (const float*)d_in[1];
    const float* ec1_s  = (const float*)d_in[2];
    const float* ec1_t  = (const float*)d_in[3];
    const float* ec2_w  = (const float*)d_in[4];
    const float* ec2_s  = (const float*)d_in[5];
    const float* ec2_t  = (const float*)d_in[6];
    const float* ec3_w  = (const float*)d_in[7];
    const float* ec3_s  = (const float*)d_in[8];
    const float* ec3_t  = (const float*)d_in[9];
    const float* ec4_w  = (const float*)d_in[10];
    const float* ec4_s  = (const float*)d_in[11];
    const float* ec4_t  = (const float*)d_in[12];
    const float* fuse_w = (const float*)d_in[13];
    const float* fuse_s = (const float*)d_in[14];
    const float* fuse_t = (const float*)d_in[15];
    const float* emb_w  = (const float*)d_in[16];
    const float* emb_s  = (const float*)d_in[17];
    const float* emb_t  = (const float*)d_in[18];
    const float* h1_w   = (const float*)d_in[19];
    const float* h1_s   = (const float*)d_in[20];
    const float* h1_t   = (const float*)d_in[21];
    const float* h2_w   = (const float*)d_in[22];
    const float* h2_s   = (const float*)d_in[23];
    const float* h2_t   = (const float*)d_in[24];
    const float* h3_w   = (const float*)d_in[25];
    const float* h3_b   = (const float*)d_in[26];
    float* out = (float*)d_out;

    float *pG, *pxcat, *pYZ, *pxloc, *pxemb, *ph1, *ph2, *pxx, *pglob, *pgb;
    __nv_bfloat16 *pXb, *pWb;
    int* pidx;
    cudaGetSymbolAddress((void**)&pG, g_G);
    cudaGetSymbolAddress((void**)&pxcat, g_xcat);
    cudaGetSymbolAddress((void**)&pYZ, g_YZ);
    cudaGetSymbolAddress((void**)&pxloc, g_xlocal);
    cudaGetSymbolAddress((void**)&pxemb, g_xemb);
    cudaGetSymbolAddress((void**)&ph1, g_h1);
    cudaGetSymbolAddress((void**)&ph2, g_h2);
    cudaGetSymbolAddress((void**)&pxx, g_xx);
    cudaGetSymbolAddress((void**)&pglob, g_glob);
    cudaGetSymbolAddress((void**)&pgb, g_gbias);
    cudaGetSymbolAddress((void**)&pXb, g_Xb);
    cudaGetSymbolAddress((void**)&pWb, g_Wb);
    cudaGetSymbolAddress((void**)&pidx, g_idx);

    // EdgeConv stack
    run_edge_layer(xyz,         3,   3,   64,  ec1_w, ec1_s, ec1_t, pG, pxx, pidx, pXb, pWb, pYZ, pxcat + 0);
    run_edge_layer(pxcat + 0,   512, 64,  64,  ec2_w, ec2_s, ec2_t, pG, pxx, pidx, pXb, pWb, pYZ, pxcat + 64);
    run_edge_layer(pxcat + 64,  512, 64,  128, ec3_w, ec3_s, ec3_t, pG, pxx, pidx, pXb, pWb, pYZ, pxcat + 128);
    run_edge_layer(pxcat + 128, 512, 128, 256, ec4_w, ec4_s, ec4_t, pG, pxx, pidx, pXb, pWb, pYZ, pxcat + 256);

    // fuse: (16384,512) -> 512, lrelu
    conv_split<<<cgrid((long)MTOT * 512), 256>>>(pxcat, 512, 512, MTOT, pXb);
    conv_split<<<cgrid(512L * 512), 256>>>(fuse_w, 512, 512, 512, pWb);
    gemm_mma<1><<<tgrid(MTOT, 512, 1), 128>>>(
        pXb, 1024, 0L, pWb, 1024, 0L, pxloc, 512, 0L,
        MTOT, 512, 512, fuse_s, fuse_t, nullptr);
    // emb: 512 -> 1024, lrelu
    conv_split<<<cgrid((long)MTOT * 512), 256>>>(pxloc, 512, 512, MTOT, pXb);
    conv_split<<<cgrid(1024L * 512), 256>>>(emb_w, 512, 512, 1024, pWb);
    gemm_mma<1><<<tgrid(MTOT, 1024, 1), 128>>>(
        pXb, 1024, 0L, pWb, 1024, 0L, pxemb, 1024, 0L,
        MTOT, 512, 1024, emb_s, emb_t, nullptr);
    // global max over N + per-batch bias via h1_w[:,512:]
    maxreduce_kernel<<<dim3(32, BATCH), 256>>>(pxemb, pglob);
    gbias_kernel<<<BATCH, 256>>>(h1_w, pglob, pgb);
    // h1: 512 -> 256 with per-batch gadd, lrelu (xloc split still in pXb)
    conv_split<<<cgrid(256L * 512), 256>>>(h1_w, 1536, 512, 256, pWb);
    gemm_mma<2><<<tgrid(MTOT, 256, 1), 128>>>(
        pXb, 1024, 0L, pWb, 1024, 0L, ph1, 256, 0L,
        MTOT, 512, 256, h1_s, h1_t, pgb);
    // h2: 256 -> 256, lrelu
    conv_split<<<cgrid((long)MTOT * 256), 256>>>(ph1, 256, 256, MTOT, pXb);
    conv_split<<<cgrid(256L * 256), 256>>>(h2_w, 256, 256, 256, pWb);
    gemm_mma<1><<<tgrid(MTOT, 256, 1), 128>>>(
        pXb, 512, 0L, pWb, 512, 0L, ph2, 256, 0L,
        MTOT, 256, 256, h2_s, h2_t, nullptr);
    // h3: 256 -> 13, +bias -> d_out
    conv_split<<<cgrid((long)MTOT * 256), 256>>>(ph2, 256, 256, MTOT, pXb);
    conv_split<<<cgrid(13L * 256), 256>>>(h3_w, 256, 256, 13, pWb);
    gemm_mma<3><<<tgrid(MTOT, 13, 1), 128>>>(
        pXb, 512, 0L, pWb, 512, 0L, out, 13, 0L,
        MTOT, 256, 13, nullptr, h3_b, nullptr);
}